// round 4
// baseline (speedup 1.0000x reference)
#include <cuda_runtime.h>
#include <cuda_bf16.h>
#include <math.h>
#include <stdint.h>

// ---------------------------------------------------------------------------
// Problem constants
// ---------------------------------------------------------------------------
#define BS 4
#define NN 256
#define DX 256
#define HH 8
#define DF 32
#define DFF 1024
#define ROWS (BS * NN)            // 1024
#define EPS 1e-5f
#define KSPLIT 4

// ---------------------------------------------------------------------------
// Device scratch (no allocations allowed)
// ---------------------------------------------------------------------------
__device__ float g_Q [ROWS * DX];
__device__ float g_K [ROWS * DX];
__device__ float g_V [ROWS * DX];
__device__ float g_T [ROWS * DX];
__device__ float g_NX[ROWS * DX];
__device__ float g_X1[ROWS * DX];
__device__ float g_H [ROWS * DFF];
__device__ float g_FF[ROWS * DX];
__device__ float g_P [KSPLIT * ROWS * DX];   // split-K partials

// ---------------------------------------------------------------------------
// Warp-MMA helpers (arch-neutral PTX, compiles to HMMA on sm_103a)
// ---------------------------------------------------------------------------
__device__ __forceinline__ void mma_bf16(float* c, const uint32_t* A, const uint32_t* B)
{
    asm volatile(
        "mma.sync.aligned.m16n8k16.row.col.f32.bf16.bf16.f32 "
        "{%0,%1,%2,%3}, {%4,%5,%6,%7}, {%8,%9}, {%0,%1,%2,%3};"
        : "+f"(c[0]), "+f"(c[1]), "+f"(c[2]), "+f"(c[3])
        : "r"(A[0]), "r"(A[1]), "r"(A[2]), "r"(A[3]), "r"(B[0]), "r"(B[1]));
}

__device__ __forceinline__ uint32_t pack_bf16(float x, float y)
{
    __nv_bfloat162 h = __floats2bfloat162_rn(x, y);
    return *(uint32_t*)&h;
}

// ---------------------------------------------------------------------------
// Tensor-core GEMM: C = A(fp32) @ B(fp32) (+bias)(+relu), bf16 hi/lo x3 split.
// Tile 128x64x32, 256 threads (8 warps, 4x2), warp tile 32x32.
// z: matrix-select (QKV) or split-K chunk (ksplit=1).
// A: [M, Ktot] row-major fp32.  B: [Ktot, N] row-major fp32 (weights).
// ---------------------------------------------------------------------------
struct TArgs {
    const float* A;
    const float* B[3];
    const float* bias[3];
    float* C[3];
    int M, N, Ktot;
    int relu, ksplit, kPerZ;
};

#define TBM 128
#define TBN 64
#define TBK 32
#define TSTR 17   // uint32 (bf16x2) stride per row = 34 bf16 (17 banks, odd)

__global__ __launch_bounds__(256)
void tgemm_kernel(TArgs a)
{
    __shared__ uint32_t sAh[TBM * TSTR];
    __shared__ uint32_t sAl[TBM * TSTR];
    __shared__ uint32_t sBh[TBN * TSTR];
    __shared__ uint32_t sBl[TBN * TSTR];

    const int tid  = threadIdx.x;
    const int lane = tid & 31;
    const int wid  = tid >> 5;
    const int wm   = wid & 3;          // 0..3  -> 32-row slab
    const int wn   = wid >> 2;         // 0..1  -> 32-col slab
    const int g    = lane >> 2;        // 0..7
    const int t    = lane & 3;         // 0..3

    const int z = blockIdx.z;
    const float* __restrict__ B;
    const float* bias;
    float* C;
    int kStart;
    if (a.ksplit) {
        B = a.B[0]; bias = nullptr;
        C = a.C[0] + (size_t)z * a.M * a.N;
        kStart = z * a.kPerZ;
    } else {
        B = a.B[z]; bias = a.bias[z]; C = a.C[z];
        kStart = 0;
    }
    const float* __restrict__ A = a.A;

    const int bm = blockIdx.y * TBM;
    const int bn = blockIdx.x * TBN;

    float acc[2][4][4] = {};

    __nv_bfloat16* sBh16 = (__nv_bfloat16*)sBh;
    __nv_bfloat16* sBl16 = (__nv_bfloat16*)sBl;

    for (int k0 = 0; k0 < a.kPerZ; k0 += TBK) {
        // ---- load A tile 128x32 fp32 -> hi/lo bf16 SMEM ----
        {
            const int kq  = (tid & 7) * 4;          // 0,4,...,28
            const int rw0 = tid >> 3;               // 0..31
            #pragma unroll
            for (int p = 0; p < 4; p++) {
                const int row = p * 32 + rw0;
                float4 v = *(const float4*)&A[(size_t)(bm + row) * a.Ktot + kStart + k0 + kq];
                float hx = __bfloat162float(__float2bfloat16(v.x));
                float hy = __bfloat162float(__float2bfloat16(v.y));
                float hz = __bfloat162float(__float2bfloat16(v.z));
                float hw = __bfloat162float(__float2bfloat16(v.w));
                const int idx = row * TSTR + (kq >> 1);
                sAh[idx]     = pack_bf16(hx, hy);
                sAh[idx + 1] = pack_bf16(hz, hw);
                sAl[idx]     = pack_bf16(v.x - hx, v.y - hy);
                sAl[idx + 1] = pack_bf16(v.z - hz, v.w - hw);
            }
        }
        // ---- load B tile 32x64 fp32 (row-major [k][n]) -> [n][k] hi/lo SMEM ----
        {
            const int nn  = tid & 63;
            const int kk0 = tid >> 6;               // 0..3
            #pragma unroll
            for (int p = 0; p < 8; p++) {
                const int kk = p * 4 + kk0;
                float v = B[(size_t)(kStart + k0 + kk) * a.N + bn + nn];
                __nv_bfloat16 h = __float2bfloat16(v);
                sBh16[nn * 34 + kk] = h;
                sBl16[nn * 34 + kk] = __float2bfloat16(v - __bfloat162float(h));
            }
        }
        __syncthreads();

        // ---- MMA phase: 2 k16 steps ----
        #pragma unroll
        for (int s = 0; s < 2; s++) {
            uint32_t ah[2][4], al[2][4], bh[4][2], bl[4][2];
            #pragma unroll
            for (int i = 0; i < 2; i++) {
                const int r = wm * 32 + i * 16 + g;
                const int base = r * TSTR + s * 8 + t;
                ah[i][0] = sAh[base];
                ah[i][1] = sAh[base + 8 * TSTR];
                ah[i][2] = sAh[base + 4];
                ah[i][3] = sAh[base + 8 * TSTR + 4];
                al[i][0] = sAl[base];
                al[i][1] = sAl[base + 8 * TSTR];
                al[i][2] = sAl[base + 4];
                al[i][3] = sAl[base + 8 * TSTR + 4];
            }
            #pragma unroll
            for (int j = 0; j < 4; j++) {
                const int n = wn * 32 + j * 8 + g;
                const int base = n * TSTR + s * 8 + t;
                bh[j][0] = sBh[base];
                bh[j][1] = sBh[base + 4];
                bl[j][0] = sBl[base];
                bl[j][1] = sBl[base + 4];
            }
            #pragma unroll
            for (int i = 0; i < 2; i++)
                #pragma unroll
                for (int j = 0; j < 4; j++) {
                    mma_bf16(acc[i][j], ah[i], bh[j]);
                    mma_bf16(acc[i][j], al[i], bh[j]);
                    mma_bf16(acc[i][j], ah[i], bl[j]);
                }
        }
        __syncthreads();
    }

    // ---- epilogue ----
    #pragma unroll
    for (int i = 0; i < 2; i++) {
        const int r0 = bm + wm * 32 + i * 16 + g;
        #pragma unroll
        for (int j = 0; j < 4; j++) {
            const int c0 = bn + wn * 32 + j * 8 + t * 2;
            float2 lo = { acc[i][j][0], acc[i][j][1] };
            float2 hi = { acc[i][j][2], acc[i][j][3] };
            if (bias) {
                lo.x += bias[c0]; lo.y += bias[c0 + 1];
                hi.x += bias[c0]; hi.y += bias[c0 + 1];
            }
            if (a.relu) {
                lo.x = fmaxf(lo.x, 0.f); lo.y = fmaxf(lo.y, 0.f);
                hi.x = fmaxf(hi.x, 0.f); hi.y = fmaxf(hi.y, 0.f);
            }
            *(float2*)&C[(size_t)r0 * a.N + c0]       = lo;
            *(float2*)&C[(size_t)(r0 + 8) * a.N + c0] = hi;
        }
    }
}

// ---------------------------------------------------------------------------
// Split-K reduce: C = sum_z P[z] + bias
// ---------------------------------------------------------------------------
__global__ __launch_bounds__(256)
void reduce4_kernel(const float* __restrict__ P, const float* __restrict__ bias,
                    float* __restrict__ C, int M, int N)
{
    const int idx = (blockIdx.x * 256 + threadIdx.x) * 4;
    const size_t total = (size_t)M * N;
    if (idx >= total) return;
    float4 s = *(const float4*)&P[idx];
    #pragma unroll
    for (int z = 1; z < KSPLIT; z++) {
        float4 p = *(const float4*)&P[(size_t)z * total + idx];
        s.x += p.x; s.y += p.y; s.z += p.z; s.w += p.w;
    }
    const int col = idx & (N - 1);
    float4 bb = *(const float4*)&bias[col];
    s.x += bb.x; s.y += bb.y; s.z += bb.z; s.w += bb.w;
    *(float4*)&C[idx] = s;
}

// ---------------------------------------------------------------------------
// Attention: per (b,i) CTA, per-dx-channel softmax over j, single pass.
// Fixed softmax shift (shift-invariant); branchless; p *= mask_j.
// ---------------------------------------------------------------------------
__global__ __launch_bounds__(256)
void attn_kernel(const float* __restrict__ Q, const float* __restrict__ K,
                 const float* __restrict__ V, const float* __restrict__ e_add,
                 const float* __restrict__ e_mul,
                 const float* __restrict__ y_add, const float* __restrict__ y_mul,
                 const float* __restrict__ mask, float* __restrict__ T)
{
    const int blk = blockIdx.x;
    const int b   = blk >> 8;
    const int dx  = threadIdx.x;

    const float scale = 0.17677669529663687f;   // 1/sqrt(32)
    const float mi = mask[blk];
    const float q  = Q[(size_t)blk * DX + dx] * mi * scale;

    const float* __restrict__ ea = e_add + (size_t)blk * (NN * DX) + dx;
    const float* __restrict__ em = e_mul + (size_t)blk * (NN * DX) + dx;
    const float* __restrict__ kb = K + (size_t)b * (NN * DX) + dx;
    const float* __restrict__ vb = V + (size_t)b * (NN * DX) + dx;
    const float* __restrict__ mrow = mask + b * NN;

    float s = 0.f, acc = 0.f;

    #pragma unroll 8
    for (int j = 0; j < NN; j++) {
        float mj  = mrow[j];
        float ee  = mi * mj;
        float emv = em[(size_t)j * DX];
        float eav = ea[(size_t)j * DX];
        float kv  = kb[(size_t)j * DX];
        float vv  = vb[(size_t)j * DX];
        float y = fmaf(q * kv, fmaf(emv, ee, 1.f), eav * ee);
        float p = __expf(y - 10.f) * mj;
        s += p;
        acc = fmaf(p, vv, acc);
    }

    float wv = acc / s;
    float t = fmaf(y_mul[b * DX + dx] + 1.f, wv, y_add[b * DX + dx]);
    T[(size_t)blk * DX + dx] = t;
}

// ---------------------------------------------------------------------------
// LayerNorm over last dim (256): out = LN(base + add * mask_row) * g + beta
// ---------------------------------------------------------------------------
__global__ __launch_bounds__(256)
void ln_kernel(const float* __restrict__ base, const float* __restrict__ add,
               const float* __restrict__ mask,
               const float* __restrict__ g, const float* __restrict__ beta,
               float* __restrict__ out)
{
    const int row = blockIdx.x;
    const int t   = threadIdx.x;

    float mrow = mask ? mask[row] : 1.f;
    float v = base[(size_t)row * DX + t] + add[(size_t)row * DX + t] * mrow;

    float s1 = v, s2 = v * v;
    #pragma unroll
    for (int o = 16; o > 0; o >>= 1) {
        s1 += __shfl_xor_sync(0xffffffffu, s1, o);
        s2 += __shfl_xor_sync(0xffffffffu, s2, o);
    }
    __shared__ float sh1[8], sh2[8];
    const int w = t >> 5, l = t & 31;
    if (l == 0) { sh1[w] = s1; sh2[w] = s2; }
    __syncthreads();
    if (w == 0) {
        float aa = (l < 8) ? sh1[l] : 0.f;
        float cc = (l < 8) ? sh2[l] : 0.f;
        #pragma unroll
        for (int o = 4; o > 0; o >>= 1) {
            aa += __shfl_xor_sync(0xffffffffu, aa, o);
            cc += __shfl_xor_sync(0xffffffffu, cc, o);
        }
        if (l == 0) { sh1[0] = aa; sh2[0] = cc; }
    }
    __syncthreads();

    float mu  = sh1[0] * (1.f / DX);
    float var = sh2[0] * (1.f / DX) - mu * mu;
    float rs  = rsqrtf(var + EPS);
    out[(size_t)row * DX + t] = fmaf((v - mu) * rs, g[t], beta[t]);
}

// ---------------------------------------------------------------------------
// Launch
// ---------------------------------------------------------------------------
extern "C" void kernel_launch(void* const* d_in, const int* in_sizes, int n_in,
                              void* d_out, int out_size)
{
    const float* X       = (const float*)d_in[0];
    const float* e_add   = (const float*)d_in[1];
    const float* e_mul   = (const float*)d_in[2];
    const float* y_x_add = (const float*)d_in[3];
    const float* y_x_mul = (const float*)d_in[4];
    const float* nmask   = (const float*)d_in[5];
    const float* Wq      = (const float*)d_in[6];
    const float* bq      = (const float*)d_in[7];
    const float* Wk      = (const float*)d_in[8];
    const float* bk      = (const float*)d_in[9];
    const float* Wv      = (const float*)d_in[10];
    const float* bv      = (const float*)d_in[11];
    const float* Wo      = (const float*)d_in[12];
    const float* bo      = (const float*)d_in[13];
    const float* W1      = (const float*)d_in[14];
    const float* b1      = (const float*)d_in[15];
    const float* W2      = (const float*)d_in[16];
    const float* b2      = (const float*)d_in[17];
    const float* g1      = (const float*)d_in[18];
    const float* beta1   = (const float*)d_in[19];
    const float* g2      = (const float*)d_in[20];
    const float* beta2   = (const float*)d_in[21];
    float* out = (float*)d_out;

    float *Qb, *Kb, *Vb, *Tb, *NXb, *X1b, *Hb, *FFb, *Pb;
    cudaGetSymbolAddress((void**)&Qb,  g_Q);
    cudaGetSymbolAddress((void**)&Kb,  g_K);
    cudaGetSymbolAddress((void**)&Vb,  g_V);
    cudaGetSymbolAddress((void**)&Tb,  g_T);
    cudaGetSymbolAddress((void**)&NXb, g_NX);
    cudaGetSymbolAddress((void**)&X1b, g_X1);
    cudaGetSymbolAddress((void**)&Hb,  g_H);
    cudaGetSymbolAddress((void**)&FFb, g_FF);
    cudaGetSymbolAddress((void**)&Pb,  g_P);

    // 1) QKV projections fused in z
    {
        TArgs t = {};
        t.A = X;
        t.B[0] = Wq; t.B[1] = Wk; t.B[2] = Wv;
        t.bias[0] = bq; t.bias[1] = bk; t.bias[2] = bv;
        t.C[0] = Qb; t.C[1] = Kb; t.C[2] = Vb;
        t.M = ROWS; t.N = DX; t.Ktot = DX; t.relu = 0; t.ksplit = 0; t.kPerZ = DX;
        dim3 grid(DX / TBN, ROWS / TBM, 3);
        tgemm_kernel<<<grid, 256>>>(t);
    }

    // 2) streaming softmax attention -> T
    attn_kernel<<<ROWS, 256>>>(Qb, Kb, Vb, e_add, e_mul, y_x_add, y_x_mul, nmask, Tb);

    // 3) NX = T @ Wo + bo
    {
        TArgs t = {};
        t.A = Tb; t.B[0] = Wo; t.bias[0] = bo; t.C[0] = NXb;
        t.M = ROWS; t.N = DX; t.Ktot = DX; t.relu = 0; t.ksplit = 0; t.kPerZ = DX;
        dim3 grid(DX / TBN, ROWS / TBM, 1);
        tgemm_kernel<<<grid, 256>>>(t);
    }

    // 4) X1 = LN(X + NX * mask)
    ln_kernel<<<ROWS, 256>>>(X, NXb, nmask, g1, beta1, X1b);

    // 5) H = relu(X1 @ W1 + b1)
    {
        TArgs t = {};
        t.A = X1b; t.B[0] = W1; t.bias[0] = b1; t.C[0] = Hb;
        t.M = ROWS; t.N = DFF; t.Ktot = DX; t.relu = 1; t.ksplit = 0; t.kPerZ = DX;
        dim3 grid(DFF / TBN, ROWS / TBM, 1);
        tgemm_kernel<<<grid, 256>>>(t);
    }

    // 6) FF partials = H @ W2 (split-K=4), then reduce + bias
    {
        TArgs t = {};
        t.A = Hb; t.B[0] = W2; t.bias[0] = nullptr; t.C[0] = Pb;
        t.M = ROWS; t.N = DX; t.Ktot = DFF; t.relu = 0; t.ksplit = 1; t.kPerZ = DFF / KSPLIT;
        dim3 grid(DX / TBN, ROWS / TBM, KSPLIT);
        tgemm_kernel<<<grid, 256>>>(t);
    }
    {
        int total4 = (ROWS * DX) / 4;
        reduce4_kernel<<<(total4 + 255) / 256, 256>>>(Pb, b2, FFb, ROWS, DX);
    }

    // 7) out = LN(X1 + FF)
    ln_kernel<<<ROWS, 256>>>(X1b, FFb, (const float*)nullptr, g2, beta2, out);
}

// round 5
// speedup vs baseline: 1.3912x; 1.3912x over previous
#include <cuda_runtime.h>
#include <cuda_bf16.h>
#include <math.h>
#include <stdint.h>

// ---------------------------------------------------------------------------
// Problem constants
// ---------------------------------------------------------------------------
#define BS 4
#define NN 256
#define DX 256
#define HH 8
#define DF 32
#define DFF 1024
#define ROWS (BS * NN)            // 1024
#define EPS 1e-5f
#define KSPLIT 4

// ---------------------------------------------------------------------------
// Device scratch (no allocations allowed)
// ---------------------------------------------------------------------------
__device__ float g_Q [ROWS * DX];
__device__ float g_K [ROWS * DX];
__device__ float g_V [ROWS * DX];
__device__ float g_T [ROWS * DX];
__device__ float g_X1[ROWS * DX];
__device__ float g_H [ROWS * DFF];
__device__ float g_P [KSPLIT * ROWS * DX];   // split-K partials

// ---------------------------------------------------------------------------
// Double-buffered SGEMM: C = A @ B (+bias later) with two modes.
// BM=BN=64, BK=16, 128 threads, 8x4 micro-tile, ping-pong SMEM, 1 sync/iter.
// mode 0: fused-N — blockIdx.x spans several output matrices (QKV);
//         matrix sel = blockIdx.x / (N/64). Bias added here.
// mode 1: split-K — blockIdx.z = K-chunk; partial written to C + z*M*N,
//         bias deferred to the consumer (fused LayerNorm).
// ---------------------------------------------------------------------------
struct GArgs {
    const float* A;
    const float* B[3];
    const float* bias[3];
    float* C[3];
    int M, N, lda;      // N = per-matrix output width; lda = A row stride (Ktot)
    int kPerZ;          // K handled per z (mode1) or total K (mode0)
    int relu, mode;
};

#define BM 64
#define BN 64
#define BKK 16

__global__ __launch_bounds__(128)
void sgemm_kernel(GArgs a)
{
    __shared__ __align__(16) float As[2][BKK][BM];
    __shared__ __align__(16) float Bs[2][BKK][BN];

    const int tid = threadIdx.x;

    const float* __restrict__ B;
    const float* bias;
    float* C;
    int kStart, bn;
    if (a.mode == 1) {
        B = a.B[0]; bias = nullptr;
        C = a.C[0] + (size_t)blockIdx.z * a.M * a.N;
        kStart = blockIdx.z * a.kPerZ;
        bn = blockIdx.x * BN;
    } else {
        const int tilesPerMat = a.N / BN;
        const int sel = blockIdx.x / tilesPerMat;
        B = a.B[sel]; bias = a.bias[sel]; C = a.C[sel];
        kStart = 0;
        bn = (blockIdx.x - sel * tilesPerMat) * BN;
    }
    const int bm = blockIdx.y * BM;

    // compute mapping: 16 col-groups x 8 row-groups
    const int colb = (tid & 15) * 4;          // 0..60
    const int rowb = (tid >> 4) * 8;          // 0..56
    // A load: row am, 8 consecutive k
    const int am = tid >> 1;                  // 0..63
    const int ak = (tid & 1) * 8;             // 0 or 8
    // B load: row bkr, 8 consecutive n
    const int bkr = tid >> 3;                 // 0..15
    const int bn8 = (tid & 7) * 8;            // 0..56

    const float* Aptr = a.A + (size_t)(bm + am) * a.lda + kStart + ak;
    const float* Bptr = B + (size_t)(kStart + bkr) * a.N + bn + bn8;

    float acc[8][4] = {};

    const int nIter = a.kPerZ / BKK;

    // prologue: stage tile 0
    float4 av0 = *(const float4*)(Aptr);
    float4 av1 = *(const float4*)(Aptr + 4);
    float4 bv0 = *(const float4*)(Bptr);
    float4 bv1 = *(const float4*)(Bptr + 4);
    As[0][ak + 0][am] = av0.x; As[0][ak + 1][am] = av0.y;
    As[0][ak + 2][am] = av0.z; As[0][ak + 3][am] = av0.w;
    As[0][ak + 4][am] = av1.x; As[0][ak + 5][am] = av1.y;
    As[0][ak + 6][am] = av1.z; As[0][ak + 7][am] = av1.w;
    *(float4*)&Bs[0][bkr][bn8]     = bv0;
    *(float4*)&Bs[0][bkr][bn8 + 4] = bv1;
    __syncthreads();

    for (int it = 0; it < nIter; it++) {
        const int cur = it & 1;
        const int nxt = cur ^ 1;
        const bool more = (it + 1) < nIter;

        if (more) {
            const int k0 = (it + 1) * BKK;
            av0 = *(const float4*)(Aptr + k0);
            av1 = *(const float4*)(Aptr + k0 + 4);
            bv0 = *(const float4*)(Bptr + (size_t)k0 * a.N);
            bv1 = *(const float4*)(Bptr + (size_t)k0 * a.N + 4);
        }

        #pragma unroll
        for (int k = 0; k < BKK; k++) {
            float4 a0 = *(const float4*)&As[cur][k][rowb];
            float4 a1 = *(const float4*)&As[cur][k][rowb + 4];
            float4 b  = *(const float4*)&Bs[cur][k][colb];
            float ar[8] = {a0.x,a0.y,a0.z,a0.w,a1.x,a1.y,a1.z,a1.w};
            float br[4] = {b.x,b.y,b.z,b.w};
            #pragma unroll
            for (int r = 0; r < 8; r++)
                #pragma unroll
                for (int c = 0; c < 4; c++)
                    acc[r][c] = fmaf(ar[r], br[c], acc[r][c]);
        }

        if (more) {
            As[nxt][ak + 0][am] = av0.x; As[nxt][ak + 1][am] = av0.y;
            As[nxt][ak + 2][am] = av0.z; As[nxt][ak + 3][am] = av0.w;
            As[nxt][ak + 4][am] = av1.x; As[nxt][ak + 5][am] = av1.y;
            As[nxt][ak + 6][am] = av1.z; As[nxt][ak + 7][am] = av1.w;
            *(float4*)&Bs[nxt][bkr][bn8]     = bv0;
            *(float4*)&Bs[nxt][bkr][bn8 + 4] = bv1;
            __syncthreads();
        }
    }

    float4 bb = {0.f, 0.f, 0.f, 0.f};
    if (bias) bb = *(const float4*)&bias[bn + colb];
    #pragma unroll
    for (int r = 0; r < 8; r++) {
        float4 o;
        o.x = acc[r][0] + bb.x;
        o.y = acc[r][1] + bb.y;
        o.z = acc[r][2] + bb.z;
        o.w = acc[r][3] + bb.w;
        if (a.relu) {
            o.x = fmaxf(o.x, 0.f); o.y = fmaxf(o.y, 0.f);
            o.z = fmaxf(o.z, 0.f); o.w = fmaxf(o.w, 0.f);
        }
        *(float4*)&C[(size_t)(bm + rowb + r) * a.N + bn + colb] = o;
    }
}

// ---------------------------------------------------------------------------
// Attention: per (b,i) CTA, per-dx-channel softmax over j, single pass.
// Fixed softmax shift (shift-invariant); branchless; p *= mask_j.
// ---------------------------------------------------------------------------
__global__ __launch_bounds__(256)
void attn_kernel(const float* __restrict__ Q, const float* __restrict__ K,
                 const float* __restrict__ V, const float* __restrict__ e_add,
                 const float* __restrict__ e_mul,
                 const float* __restrict__ y_add, const float* __restrict__ y_mul,
                 const float* __restrict__ mask, float* __restrict__ T)
{
    const int blk = blockIdx.x;
    const int b   = blk >> 8;
    const int dx  = threadIdx.x;

    const float scale = 0.17677669529663687f;   // 1/sqrt(32)
    const float mi = mask[blk];
    const float q  = Q[(size_t)blk * DX + dx] * mi * scale;

    const float* __restrict__ ea = e_add + (size_t)blk * (NN * DX) + dx;
    const float* __restrict__ em = e_mul + (size_t)blk * (NN * DX) + dx;
    const float* __restrict__ kb = K + (size_t)b * (NN * DX) + dx;
    const float* __restrict__ vb = V + (size_t)b * (NN * DX) + dx;
    const float* __restrict__ mrow = mask + b * NN;

    float s = 0.f, acc = 0.f;

    #pragma unroll 8
    for (int j = 0; j < NN; j++) {
        float mj  = mrow[j];
        float ee  = mi * mj;
        float emv = em[(size_t)j * DX];
        float eav = ea[(size_t)j * DX];
        float kv  = kb[(size_t)j * DX];
        float vv  = vb[(size_t)j * DX];
        float y = fmaf(q * kv, fmaf(emv, ee, 1.f), eav * ee);
        float p = __expf(y - 10.f) * mj;
        s += p;
        acc = fmaf(p, vv, acc);
    }

    float wv = acc / s;
    float t = fmaf(y_mul[b * DX + dx] + 1.f, wv, y_add[b * DX + dx]);
    T[(size_t)blk * DX + dx] = t;
}

// ---------------------------------------------------------------------------
// Fused split-K reduce + bias + residual + LayerNorm:
// v = base[row,t] + mask_row * (sum_z P[z][row,t] + bias[t])
// out = LN(v) * g + beta.  One CTA per row, 256 threads.
// ---------------------------------------------------------------------------
__global__ __launch_bounds__(256)
void ln_kernel(const float* __restrict__ base, const float* __restrict__ P,
               int nsplit, const float* __restrict__ bias,
               const float* __restrict__ mask,
               const float* __restrict__ g, const float* __restrict__ beta,
               float* __restrict__ out)
{
    const int row = blockIdx.x;
    const int t   = threadIdx.x;
    const size_t MN = (size_t)ROWS * DX;
    const size_t off = (size_t)row * DX + t;

    float add = bias[t];
    #pragma unroll 4
    for (int z = 0; z < nsplit; z++)
        add += P[z * MN + off];

    float mrow = mask ? mask[row] : 1.f;
    float v = base[off] + add * mrow;

    float s1 = v, s2 = v * v;
    #pragma unroll
    for (int o = 16; o > 0; o >>= 1) {
        s1 += __shfl_xor_sync(0xffffffffu, s1, o);
        s2 += __shfl_xor_sync(0xffffffffu, s2, o);
    }
    __shared__ float sh1[8], sh2[8];
    const int w = t >> 5, l = t & 31;
    if (l == 0) { sh1[w] = s1; sh2[w] = s2; }
    __syncthreads();
    if (w == 0) {
        float aa = (l < 8) ? sh1[l] : 0.f;
        float cc = (l < 8) ? sh2[l] : 0.f;
        #pragma unroll
        for (int o = 4; o > 0; o >>= 1) {
            aa += __shfl_xor_sync(0xffffffffu, aa, o);
            cc += __shfl_xor_sync(0xffffffffu, cc, o);
        }
        if (l == 0) { sh1[0] = aa; sh2[0] = cc; }
    }
    __syncthreads();

    float mu  = sh1[0] * (1.f / DX);
    float var = sh2[0] * (1.f / DX) - mu * mu;
    float rs  = rsqrtf(var + EPS);
    out[off] = fmaf((v - mu) * rs, g[t], beta[t]);
}

// ---------------------------------------------------------------------------
// Launch
// ---------------------------------------------------------------------------
extern "C" void kernel_launch(void* const* d_in, const int* in_sizes, int n_in,
                              void* d_out, int out_size)
{
    const float* X       = (const float*)d_in[0];
    const float* e_add   = (const float*)d_in[1];
    const float* e_mul   = (const float*)d_in[2];
    const float* y_x_add = (const float*)d_in[3];
    const float* y_x_mul = (const float*)d_in[4];
    const float* nmask   = (const float*)d_in[5];
    const float* Wq      = (const float*)d_in[6];
    const float* bq      = (const float*)d_in[7];
    const float* Wk      = (const float*)d_in[8];
    const float* bk      = (const float*)d_in[9];
    const float* Wv      = (const float*)d_in[10];
    const float* bv      = (const float*)d_in[11];
    const float* Wo      = (const float*)d_in[12];
    const float* bo      = (const float*)d_in[13];
    const float* W1      = (const float*)d_in[14];
    const float* b1      = (const float*)d_in[15];
    const float* W2      = (const float*)d_in[16];
    const float* b2      = (const float*)d_in[17];
    const float* g1      = (const float*)d_in[18];
    const float* beta1   = (const float*)d_in[19];
    const float* g2      = (const float*)d_in[20];
    const float* beta2   = (const float*)d_in[21];
    float* out = (float*)d_out;

    float *Qb, *Kb, *Vb, *Tb, *X1b, *Hb, *Pb;
    cudaGetSymbolAddress((void**)&Qb,  g_Q);
    cudaGetSymbolAddress((void**)&Kb,  g_K);
    cudaGetSymbolAddress((void**)&Vb,  g_V);
    cudaGetSymbolAddress((void**)&Tb,  g_T);
    cudaGetSymbolAddress((void**)&X1b, g_X1);
    cudaGetSymbolAddress((void**)&Hb,  g_H);
    cudaGetSymbolAddress((void**)&Pb,  g_P);

    // 1) QKV projections, fused along N (192 CTAs)
    {
        GArgs a = {};
        a.A = X;
        a.B[0] = Wq; a.B[1] = Wk; a.B[2] = Wv;
        a.bias[0] = bq; a.bias[1] = bk; a.bias[2] = bv;
        a.C[0] = Qb; a.C[1] = Kb; a.C[2] = Vb;
        a.M = ROWS; a.N = DX; a.lda = DX; a.kPerZ = DX; a.relu = 0; a.mode = 0;
        dim3 grid(3 * DX / BN, ROWS / BM, 1);
        sgemm_kernel<<<grid, 128>>>(a);
    }

    // 2) streaming softmax attention -> T
    attn_kernel<<<ROWS, 256>>>(Qb, Kb, Vb, e_add, e_mul, y_x_add, y_x_mul, nmask, Tb);

    // 3) Wo partials (split-K=2, 128 CTAs); bias folded into LN1
    {
        GArgs a = {};
        a.A = Tb; a.B[0] = Wo; a.C[0] = Pb;
        a.M = ROWS; a.N = DX; a.lda = DX; a.kPerZ = DX / 2; a.relu = 0; a.mode = 1;
        dim3 grid(DX / BN, ROWS / BM, 2);
        sgemm_kernel<<<grid, 128>>>(a);
    }

    // 4) X1 = LN(X + mask*(sum P + bo))
    ln_kernel<<<ROWS, 256>>>(X, Pb, 2, bo, nmask, g1, beta1, X1b);

    // 5) H = relu(X1 @ W1 + b1)  (256 CTAs)
    {
        GArgs a = {};
        a.A = X1b; a.B[0] = W1; a.bias[0] = b1; a.C[0] = Hb;
        a.M = ROWS; a.N = DFF; a.lda = DX; a.kPerZ = DX; a.relu = 1; a.mode = 0;
        dim3 grid(DFF / BN, ROWS / BM, 1);
        sgemm_kernel<<<grid, 128>>>(a);
    }

    // 6) W2 partials (split-K=4, 256 CTAs); bias folded into LN2
    {
        GArgs a = {};
        a.A = Hb; a.B[0] = W2; a.C[0] = Pb;
        a.M = ROWS; a.N = DX; a.lda = DFF; a.kPerZ = DFF / KSPLIT; a.relu = 0; a.mode = 1;
        dim3 grid(DX / BN, ROWS / BM, KSPLIT);
        sgemm_kernel<<<grid, 128>>>(a);
    }

    // 7) out = LN(X1 + sum P + b2)
    ln_kernel<<<ROWS, 256>>>(X1b, Pb, KSPLIT, b2, (const float*)nullptr, g2, beta2, out);
}